// round 10
// baseline (speedup 1.0000x reference)
#include <cuda_runtime.h>

#define XSIZE 256

// 128 threads/block (thread = patch column), each block loops over 8 patch rows.
// The loop is deliberately NOT unrolled: per-iteration MUFU-slot queueing makes
// warps drift out of program phase, so at steady state each SMSP issues MUFU
// (phase sincos) from some warps while issuing FMA (butterflies) from others.
__global__ __launch_bounds__(128) void qconv_kernel8(const float* __restrict__ x,
                                                     const float* __restrict__ w,
                                                     float* __restrict__ out)
{
    __shared__ float sh[5];   // tau0..3, scale
    if (threadIdx.x == 0) {
        float C = 1.0f;
#pragma unroll
        for (int q = 0; q < 4; q++) {
            float cq, sq;
            __sincosf(0.5f * __ldg(w + q), &sq, &cq);
            sh[q] = __fdividef(sq, cq);     // tan(w_q/2)
            C *= cq;
        }
        sh[4] = 0.0625f * C * C;            // prod cos^2 folded into prob scale
    }
    __syncthreads();
    const float u0 = sh[0], u1 = sh[1], u2 = sh[2], u3 = sh[3];
    const float scale = sh[4];

    const int col = threadIdx.x;            // 0..127
    const int b   = blockIdx.x >> 4;
    const int g   = blockIdx.x & 15;        // row group: rows 8g..8g+7

#pragma unroll 1
    for (int it = 0; it < 8; it++) {
        const int i = g * 8 + it;           // patch row 0..127
        const size_t base = ((size_t)b * XSIZE + 2 * i) * XSIZE + 2 * col;
        const float2 r0 = *reinterpret_cast<const float2*>(x + base);
        const float2 r1 = *reinterpret_cast<const float2*>(x + base + XSIZE);
        const float x0 = r0.x, x1 = r0.y, x2 = r1.x, x3 = r1.y;

        // t_e = x3 ± x2 ± x1 ± x0 (bit2->x2, bit1->x1, bit0->x0)
        const float ap = x3 + x2, am = x3 - x2;
        const float bp = x1 + x0, bm = x1 - x0;
        float t[8];
        t[0] = am - bp;  t[1] = am - bm;  t[2] = am + bm;  t[3] = am + bp;
        t[4] = ap - bp;  t[5] = ap - bm;  t[6] = ap + bm;  t[7] = ap + bp;

        // diag pair (8|e, e^7): phi = -h^2 ∓ h, h = t_e/2 (global phase dropped)
        float vr[16], vi[16];
#pragma unroll
        for (int e = 0; e < 8; e++) {
            const float h  = 0.5f * t[e];
            const float p1 = __fmaf_rn(-h, h, -h);
            const float p0 = __fmaf_rn(-h, h,  h);
            __sincosf(p1, &vi[8 | e], &vr[8 | e]);
            __sincosf(p0, &vi[e ^ 7], &vr[e ^ 7]);
        }

        // RX butterflies, tangent form (4 fma each); cos factors in scale.
        const float tau[4] = {u0, u1, u2, u3};
#pragma unroll
        for (int q = 0; q < 4; q++) {
            const float tq = tau[q];
#pragma unroll
            for (int m = 0; m < 8; m++) {
                const int j0 = ((m >> q) << (q + 1)) | (m & ((1 << q) - 1));
                const int j1 = j0 | (1 << q);
                const float ar = vr[j0], ai = vi[j0];
                const float br = vr[j1], bim = vi[j1];
                vr[j0] = __fmaf_rn( tq, bim, ar);
                vi[j0] = __fmaf_rn(-tq, br,  ai);
                vr[j1] = __fmaf_rn( tq, ai,  br);
                vi[j1] = __fmaf_rn(-tq, ar,  bim);
            }
        }

        // CNOT ring + per-qubit Z readout = parity-masked probability sums.
        float o0 = 0.f, o1 = 0.f, o2 = 0.f, o3 = 0.f;
#pragma unroll
        for (int k = 0; k < 16; k++) {
            const float p = __fmaf_rn(vr[k], vr[k], vi[k] * vi[k]);
            if (__popc(k & 0xF) & 1) o0 += p;
            if (__popc(k & 0x7) & 1) o1 += p;
            if (__popc(k & 0x3) & 1) o2 += p;
            if (__popc(k & 0xE) & 1) o3 += p;
        }

        float4 o;
        o.x = scale * o0;
        o.y = scale * o1;
        o.z = scale * o2;
        o.w = scale * o3;
        reinterpret_cast<float4*>(out)[((size_t)b * 128 + i) * 128 + col] = o;
    }
}

extern "C" void kernel_launch(void* const* d_in, const int* in_sizes, int n_in,
                              void* d_out, int out_size)
{
    const float* x = (const float*)d_in[0];
    const float* w = (const float*)d_in[1];
    float* out = (float*)d_out;
    const int batch = in_sizes[0] / (XSIZE * XSIZE);
    qconv_kernel8<<<batch * 16, 128>>>(x, w, out);
}

// round 11
// speedup vs baseline: 1.1214x; 1.1214x over previous
#include <cuda_runtime.h>

#define XSIZE 256
#define NB 128

__device__ __forceinline__ float fadd(float a, float b) { return __fadd_rn(a, b); }

// 1 patch/thread, 128 threads/block (R1 layout: best measured issue efficiency).
// All pure additions written as __fadd_rn so they emit FADD (candidate for the
// ALU dispatch port) instead of being fused into FFMA (FMA port, rt_SMSP=2).
__global__ __launch_bounds__(128) void qconv_kernel9(const float* __restrict__ x,
                                                     const float* __restrict__ w,
                                                     float* __restrict__ out)
{
    __shared__ float sh[5];   // tau0..3, scale
    if (threadIdx.x == 0) {
        float C = 1.0f;
#pragma unroll
        for (int q = 0; q < 4; q++) {
            float cq, sq;
            __sincosf(0.5f * __ldg(w + q), &sq, &cq);
            sh[q] = __fdividef(sq, cq);     // tan(w_q/2)
            C *= cq;
        }
        sh[4] = 0.0625f * C * C;            // prod cos^2 folded into prob scale
    }
    __syncthreads();

    const int col = threadIdx.x;            // 0..127
    const int bi  = blockIdx.x;             // b*128 + i
    const int i   = bi & (NB - 1);
    const size_t base = ((size_t)(bi >> 7) * XSIZE + 2 * i) * XSIZE + 2 * col;
    const float2 r0 = *reinterpret_cast<const float2*>(x + base);
    const float2 r1 = *reinterpret_cast<const float2*>(x + base + XSIZE);

    // halved inputs: h_e = y3 ± y2 ± y1 ± y0 directly gives h = t_e/2
    const float y0 = 0.5f * r0.x, y1 = 0.5f * r0.y;
    const float y2 = 0.5f * r1.x, y3 = 0.5f * r1.y;
    const float ap = fadd(y3,  y2), am = fadd(y3, -y2);
    const float bp = fadd(y1,  y0), bm = fadd(y1, -y0);
    float h[8];
    h[0] = fadd(am, -bp);  h[1] = fadd(am, -bm);
    h[2] = fadd(am,  bm);  h[3] = fadd(am,  bp);
    h[4] = fadd(ap, -bp);  h[5] = fadd(ap, -bm);
    h[6] = fadd(ap,  bm);  h[7] = fadd(ap,  bp);

    // diag pair (8|e, e^7): phi = -h^2 ∓ h (global S/4 phase dropped)
    float vr[16], vi[16];
#pragma unroll
    for (int e = 0; e < 8; e++) {
        const float he = h[e];
        const float p1 = __fmaf_rn(he, -he, -he);   // -h^2 - h
        const float p0 = __fmaf_rn(he, -he,  he);   // -h^2 + h
        __sincosf(p1, &vi[8 | e], &vr[8 | e]);
        __sincosf(p0, &vi[e ^ 7], &vr[e ^ 7]);
    }

    const float tau[4] = {sh[0], sh[1], sh[2], sh[3]};
    const float scale  = sh[4];

    // RX butterflies, tangent form (4 FFMA each); cos factors folded in scale.
#pragma unroll
    for (int q = 0; q < 4; q++) {
        const float tq = tau[q];
#pragma unroll
        for (int m = 0; m < 8; m++) {
            const int j0 = ((m >> q) << (q + 1)) | (m & ((1 << q) - 1));
            const int j1 = j0 | (1 << q);
            const float ar = vr[j0], ai = vi[j0];
            const float br = vr[j1], bim = vi[j1];
            vr[j0] = __fmaf_rn( tq, bim, ar);
            vi[j0] = __fmaf_rn(-tq, br,  ai);
            vr[j1] = __fmaf_rn( tq, ai,  br);
            vi[j1] = __fmaf_rn(-tq, ar,  bim);
        }
    }

    // CNOT ring + per-qubit Z readout = parity-masked probability sums.
    // Squares on the FMA port; the 32 accumulations as FADD (ALU-port candidate).
    float o0 = 0.f, o1 = 0.f, o2 = 0.f, o3 = 0.f;
#pragma unroll
    for (int k = 0; k < 16; k++) {
        const float p = __fmaf_rn(vr[k], vr[k], vi[k] * vi[k]);
        if (__popc(k & 0xF) & 1) o0 = fadd(o0, p);
        if (__popc(k & 0x7) & 1) o1 = fadd(o1, p);
        if (__popc(k & 0x3) & 1) o2 = fadd(o2, p);
        if (__popc(k & 0xE) & 1) o3 = fadd(o3, p);
    }

    float4 o;
    o.x = scale * o0;
    o.y = scale * o1;
    o.z = scale * o2;
    o.w = scale * o3;
    reinterpret_cast<float4*>(out)[(size_t)bi * NB + col] = o;
}

extern "C" void kernel_launch(void* const* d_in, const int* in_sizes, int n_in,
                              void* d_out, int out_size)
{
    const float* x = (const float*)d_in[0];
    const float* w = (const float*)d_in[1];
    float* out = (float*)d_out;
    const int batch = in_sizes[0] / (XSIZE * XSIZE);
    qconv_kernel9<<<batch * NB, NB>>>(x, w, out);
}